// round 7
// baseline (speedup 1.0000x reference)
#include <cuda_runtime.h>

#define NN 50000
#define EE 800000
#define SB 256
#define NBLK ((NN + SB - 1) / SB)   // 196

typedef unsigned long long ull;

// ---------------- device scratch (static only) ----------------
__device__ int    d_is64;
__device__ int    d_cnt[NN];
__device__ int    d_cursor[NN];
__device__ int    d_rowptr[NN + 1];
__device__ int    d_col[EE];
__device__ int    d_bsum[SB];
__device__ float4 d_agg4[NN * 32];   // [NN,128]
__device__ float4 d_h1_4[NN * 32];   // [NN,128]
__device__ float4 d_h2_4[NN * 16];   // [NN,64]
__device__ float4 d_y_4[NN * 16];    // [NN,64]

// ---------------- f32x2 helpers ----------------
__device__ __forceinline__ void ffma2(ull& d, ull a, ull b) {
    asm("fma.rn.f32x2 %0, %1, %2, %0;" : "+l"(d) : "l"(a), "l"(b));
}
__device__ __forceinline__ ull dup2(float v) {
    unsigned int u = __float_as_uint(v);
    return ((ull)u << 32) | (ull)u;
}
__device__ __forceinline__ float2 unpk(ull p) {
    float2 r;
    r.x = __uint_as_float((unsigned int)p);
    r.y = __uint_as_float((unsigned int)(p >> 32));
    return r;
}

// ---------------- edge-index dtype probe ----------------
__global__ void k_probe(const int* __restrict__ ei) {
    __shared__ int nonzero;
    if (threadIdx.x == 0) nonzero = 0;
    __syncthreads();
    for (int i = threadIdx.x; i < 4096; i += blockDim.x)
        if (ei[2 * i + 1] != 0) nonzero = 1;
    __syncthreads();
    if (threadIdx.x == 0) d_is64 = (nonzero == 0) ? 1 : 0;
}

__device__ __forceinline__ int edge_id(const void* ei, int which, int e) {
    if (d_is64) return (int)((const long long*)ei)[(size_t)which * EE + e];
    return ((const int*)ei)[(size_t)which * EE + e];
}

// ---------------- CSR build ----------------
__global__ void k_zero() {
    int i = blockIdx.x * blockDim.x + threadIdx.x;
    if (i < NN) { d_cnt[i] = 0; d_cursor[i] = 0; }
}

__global__ void k_count(const void* __restrict__ ei) {
    int e = blockIdx.x * blockDim.x + threadIdx.x;
    if (e < EE) atomicAdd(&d_cnt[edge_id(ei, 1, e)], 1);
}

__global__ void k_scan1() {
    __shared__ int s[SB];
    int tid = threadIdx.x;
    int i = blockIdx.x * SB + tid;
    int v = (i < NN) ? d_cnt[i] : 0;
    s[tid] = v;
    __syncthreads();
    for (int off = 1; off < SB; off <<= 1) {
        int t = (tid >= off) ? s[tid - off] : 0;
        __syncthreads();
        s[tid] += t;
        __syncthreads();
    }
    if (i < NN) d_rowptr[i] = s[tid] - v;
    if (tid == SB - 1) d_bsum[blockIdx.x] = s[tid];
}

__global__ void k_scan2() {
    __shared__ int s[SB];
    int tid = threadIdx.x;
    int v = (tid < NBLK) ? d_bsum[tid] : 0;
    s[tid] = v;
    __syncthreads();
    for (int off = 1; off < SB; off <<= 1) {
        int t = (tid >= off) ? s[tid - off] : 0;
        __syncthreads();
        s[tid] += t;
        __syncthreads();
    }
    if (tid < NBLK) d_bsum[tid] = s[tid] - v;
}

__global__ void k_scan3() {
    int tid = threadIdx.x;
    int i = blockIdx.x * SB + tid;
    if (i < NN) d_rowptr[i] += d_bsum[blockIdx.x];
    if (i == 0) d_rowptr[NN] = EE;
}

__global__ void k_fill(const void* __restrict__ ei) {
    int e = blockIdx.x * blockDim.x + threadIdx.x;
    if (e < EE) {
        int d = edge_id(ei, 1, e);
        int s = edge_id(ei, 0, e);
        int p = atomicAdd(&d_cursor[d], 1);
        d_col[d_rowptr[d] + p] = s;
    }
}

// ---------------- neighbor mean aggregation (128 features, warp per node) ----------------
__global__ void k_agg_mean(const float* xext, int use_h1) {
    const float4* x4 = use_h1 ? (const float4*)d_h1_4 : (const float4*)xext;
    int idx = blockIdx.x * blockDim.x + threadIdx.x;
    int node = idx >> 5;
    int lane = idx & 31;
    if (node >= NN) return;
    int beg = d_rowptr[node], end = d_rowptr[node + 1];
    float4 acc = make_float4(0.f, 0.f, 0.f, 0.f);
    for (int j = beg; j < end; j++) {
        int s = d_col[j];
        float4 v = x4[(size_t)s * 32 + lane];
        acc.x += v.x; acc.y += v.y; acc.z += v.z; acc.w += v.w;
    }
    int c = end - beg;
    float inv = 1.0f / (float)(c > 0 ? c : 1);
    acc.x *= inv; acc.y *= inv; acc.z *= inv; acc.w *= inv;
    d_agg4[(size_t)node * 32 + lane] = acc;
}

// ------------- layer1 GEMM (FFMA2): h1 = relu(agg @ W1l + x @ W1r + b1l) ------------------
// virtual K = 256; BM=64, BN=128, 256 threads, micro-tile 8 rows x 4 cols (2x f32x2).
__global__ void __launch_bounds__(256) k_gemm_relu128(
    const float* __restrict__ x,
    const float* __restrict__ W1, const float* __restrict__ W2,
    const float* __restrict__ bias)
{
    __shared__ __align__(16) float Ws[16][128];
    __shared__ __align__(16) float AsD[16 * 132];
    int tid = threadIdx.x;
    int rowBase = blockIdx.x * 64;
    int rg = tid >> 5;   // 0..7  -> rows rg*8..+7
    int cg = tid & 31;   // 0..31 -> cols cg*4..+3
    ull acc[8][2];
#pragma unroll
    for (int i = 0; i < 8; i++) { acc[i][0] = 0ull; acc[i][1] = 0ull; }

    int lr = tid >> 2;           // 0..63 (row within tile)
    int lc = (tid & 3) * 4;      // 0,4,8,12 (k within tile)
    bool lvalid = (rowBase + lr) < NN;

    for (int kk = 0; kk < 256; kk += 16) {
        const float* A = (kk < 128) ? (const float*)d_agg4 : x;
        const float* W = (kk < 128) ? W1 : W2;
        int k0 = kk & 127;
        float4 va = make_float4(0.f, 0.f, 0.f, 0.f);
        if (lvalid) va = *(const float4*)(A + (size_t)(rowBase + lr) * 128 + k0 + lc);
        *(ull*)&AsD[(lc + 0) * 132 + 2 * lr] = dup2(va.x);
        *(ull*)&AsD[(lc + 1) * 132 + 2 * lr] = dup2(va.y);
        *(ull*)&AsD[(lc + 2) * 132 + 2 * lr] = dup2(va.z);
        *(ull*)&AsD[(lc + 3) * 132 + 2 * lr] = dup2(va.w);
#pragma unroll
        for (int it = 0; it < 2; it++) {
            int idx = tid + it * 256;
            int wr = idx >> 5;
            int wc = (idx & 31) * 4;
            *(float4*)&Ws[wr][wc] = *(const float4*)(W + (size_t)(k0 + wr) * 128 + wc);
        }
        __syncthreads();
#pragma unroll
        for (int k = 0; k < 16; k++) {
            ulonglong2 bv = *(const ulonglong2*)&Ws[k][cg * 4];
#pragma unroll
            for (int i = 0; i < 8; i++) {
                ull av = *(const ull*)&AsD[k * 132 + 2 * (rg * 8 + i)];
                ffma2(acc[i][0], av, bv.x);
                ffma2(acc[i][1], av, bv.y);
            }
        }
        __syncthreads();
    }
    float4 bb = *(const float4*)(bias + cg * 4);
#pragma unroll
    for (int i = 0; i < 8; i++) {
        int r = rowBase + rg * 8 + i;
        if (r < NN) {
            float2 p0 = unpk(acc[i][0]);
            float2 p1 = unpk(acc[i][1]);
            float4 v;
            v.x = fmaxf(p0.x + bb.x, 0.f);
            v.y = fmaxf(p0.y + bb.y, 0.f);
            v.z = fmaxf(p1.x + bb.z, 0.f);
            v.w = fmaxf(p1.y + bb.w, 0.f);
            *((float4*)d_h1_4 + (size_t)r * 32 + cg) = v;
        }
    }
}

// ------------- layer2 GEMM (FFMA2): h2 = agg2 @ W2l + h1 @ W2r + b2l ----------------------
// virtual K = 256; BM=64, BN=64, 256 threads, micro-tile 4 rows x 4 cols.
__global__ void __launch_bounds__(256) k_gemm_64(
    const float* __restrict__ W1, const float* __restrict__ W2,
    const float* __restrict__ bias)
{
    __shared__ __align__(16) float Ws[16][64];
    __shared__ __align__(16) float AsD[16 * 132];
    int tid = threadIdx.x;
    int rowBase = blockIdx.x * 64;
    int rg = tid >> 4;   // 0..15 -> rows rg*4..+3
    int cg = tid & 15;   // cols cg*4..+3
    ull acc[4][2];
#pragma unroll
    for (int i = 0; i < 4; i++) { acc[i][0] = 0ull; acc[i][1] = 0ull; }

    int lr = tid >> 2;
    int lc = (tid & 3) * 4;
    bool lvalid = (rowBase + lr) < NN;

    for (int kk = 0; kk < 256; kk += 16) {
        const float* A = (kk < 128) ? (const float*)d_agg4 : (const float*)d_h1_4;
        const float* W = (kk < 128) ? W1 : W2;
        int k0 = kk & 127;
        float4 va = make_float4(0.f, 0.f, 0.f, 0.f);
        if (lvalid) va = *(const float4*)(A + (size_t)(rowBase + lr) * 128 + k0 + lc);
        *(ull*)&AsD[(lc + 0) * 132 + 2 * lr] = dup2(va.x);
        *(ull*)&AsD[(lc + 1) * 132 + 2 * lr] = dup2(va.y);
        *(ull*)&AsD[(lc + 2) * 132 + 2 * lr] = dup2(va.z);
        *(ull*)&AsD[(lc + 3) * 132 + 2 * lr] = dup2(va.w);
        {
            int wr = tid >> 4;
            int wc = (tid & 15) * 4;
            *(float4*)&Ws[wr][wc] = *(const float4*)(W + (size_t)(k0 + wr) * 64 + wc);
        }
        __syncthreads();
#pragma unroll
        for (int k = 0; k < 16; k++) {
            ulonglong2 bv = *(const ulonglong2*)&Ws[k][cg * 4];
#pragma unroll
            for (int i = 0; i < 4; i++) {
                ull av = *(const ull*)&AsD[k * 132 + 2 * (rg * 4 + i)];
                ffma2(acc[i][0], av, bv.x);
                ffma2(acc[i][1], av, bv.y);
            }
        }
        __syncthreads();
    }
    float4 bb = *(const float4*)(bias + cg * 4);
#pragma unroll
    for (int i = 0; i < 4; i++) {
        int r = rowBase + rg * 4 + i;
        if (r < NN) {
            float2 p0 = unpk(acc[i][0]);
            float2 p1 = unpk(acc[i][1]);
            float4 v = make_float4(p0.x + bb.x, p0.y + bb.y, p1.x + bb.z, p1.y + bb.w);
            *((float4*)d_h2_4 + (size_t)r * 16 + cg) = v;
        }
    }
}

// ---------------- row softmax over 64 cols, in place on d_h2, warp per row ----------------
__global__ void k_softmax() {
    int idx = blockIdx.x * blockDim.x + threadIdx.x;
    int row = idx >> 5;
    int lane = idx & 31;
    if (row >= NN) return;
    float* p = (float*)d_h2_4 + (size_t)row * 64;
    float v0 = p[lane], v1 = p[lane + 32];
    float m = fmaxf(v0, v1);
    for (int o = 16; o > 0; o >>= 1) m = fmaxf(m, __shfl_xor_sync(0xffffffffu, m, o));
    float e0 = __expf(v0 - m), e1 = __expf(v1 - m);
    float s = e0 + e1;
    for (int o = 16; o > 0; o >>= 1) s += __shfl_xor_sync(0xffffffffu, s, o);
    float inv = 1.0f / s;
    p[lane] = e0 * inv;
    p[lane + 32] = e1 * inv;
}

// ---------------- GCN GEMM (FFMA2): y = (h2 @ Wg) * dinv[row]; K = 64 --------------------
__global__ void __launch_bounds__(256) k_gemm_gcn(const float* __restrict__ Wg) {
    __shared__ __align__(16) float Ws[16][64];
    __shared__ __align__(16) float AsD[16 * 132];
    int tid = threadIdx.x;
    int rowBase = blockIdx.x * 64;
    int rg = tid >> 4;
    int cg = tid & 15;
    ull acc[4][2];
#pragma unroll
    for (int i = 0; i < 4; i++) { acc[i][0] = 0ull; acc[i][1] = 0ull; }

    int lr = tid >> 2;
    int lc = (tid & 3) * 4;
    bool lvalid = (rowBase + lr) < NN;
    const float* A = (const float*)d_h2_4;

    for (int kk = 0; kk < 64; kk += 16) {
        float4 va = make_float4(0.f, 0.f, 0.f, 0.f);
        if (lvalid) va = *(const float4*)(A + (size_t)(rowBase + lr) * 64 + kk + lc);
        *(ull*)&AsD[(lc + 0) * 132 + 2 * lr] = dup2(va.x);
        *(ull*)&AsD[(lc + 1) * 132 + 2 * lr] = dup2(va.y);
        *(ull*)&AsD[(lc + 2) * 132 + 2 * lr] = dup2(va.z);
        *(ull*)&AsD[(lc + 3) * 132 + 2 * lr] = dup2(va.w);
        {
            int wr = tid >> 4;
            int wc = (tid & 15) * 4;
            *(float4*)&Ws[wr][wc] = *(const float4*)(Wg + (size_t)(kk + wr) * 64 + wc);
        }
        __syncthreads();
#pragma unroll
        for (int k = 0; k < 16; k++) {
            ulonglong2 bv = *(const ulonglong2*)&Ws[k][cg * 4];
#pragma unroll
            for (int i = 0; i < 4; i++) {
                ull av = *(const ull*)&AsD[k * 132 + 2 * (rg * 4 + i)];
                ffma2(acc[i][0], av, bv.x);
                ffma2(acc[i][1], av, bv.y);
            }
        }
        __syncthreads();
    }
#pragma unroll
    for (int i = 0; i < 4; i++) {
        int r = rowBase + rg * 4 + i;
        if (r < NN) {
            float dinv = rsqrtf((float)(d_cnt[r] + 1));
            float2 p0 = unpk(acc[i][0]);
            float2 p1 = unpk(acc[i][1]);
            float4 v = make_float4(p0.x * dinv, p0.y * dinv, p1.x * dinv, p1.y * dinv);
            d_y_4[(size_t)r * 16 + cg] = v;
        }
    }
}

// ---------------- GCN aggregation: out[i] = dinv[i]*(y[i] + sum_{j in N(i)} y[j]) + bg ----
__global__ void k_gcn_agg(const float* __restrict__ bg, float* __restrict__ out) {
    int idx = blockIdx.x * blockDim.x + threadIdx.x;
    int node = idx >> 4;
    int lane = idx & 15;
    if (node >= NN) return;
    const float4* y4 = (const float4*)d_y_4;
    float4 acc = y4[(size_t)node * 16 + lane];  // self loop
    int beg = d_rowptr[node], end = d_rowptr[node + 1];
    for (int j = beg; j < end; j++) {
        int s = d_col[j];
        float4 v = y4[(size_t)s * 16 + lane];
        acc.x += v.x; acc.y += v.y; acc.z += v.z; acc.w += v.w;
    }
    float dinv = rsqrtf((float)(d_cnt[node] + 1));
    float4 b = ((const float4*)bg)[lane];
    float4 o;
    o.x = acc.x * dinv + b.x;
    o.y = acc.y * dinv + b.y;
    o.z = acc.z * dinv + b.z;
    o.w = acc.w * dinv + b.w;
    ((float4*)out)[(size_t)node * 16 + lane] = o;
}

// ---------------- launch ----------------
extern "C" void kernel_launch(void* const* d_in, const int* in_sizes, int n_in,
                              void* d_out, int out_size) {
    const float* x = (const float*)d_in[0];
    const void* ei = d_in[1];
    const float* W1l = (const float*)d_in[2];
    const float* b1l = (const float*)d_in[3];
    const float* W1r = (const float*)d_in[4];
    const float* W2l = (const float*)d_in[5];
    const float* b2l = (const float*)d_in[6];
    const float* W2r = (const float*)d_in[7];
    const float* Wg  = (const float*)d_in[8];
    const float* bg  = (const float*)d_in[9];
    float* out = (float*)d_out;

    // dtype probe + CSR build
    k_probe<<<1, 256>>>((const int*)ei);
    k_zero<<<(NN + 255) / 256, 256>>>();
    k_count<<<(EE + 255) / 256, 256>>>(ei);
    k_scan1<<<NBLK, SB>>>();
    k_scan2<<<1, SB>>>();
    k_scan3<<<NBLK, SB>>>();
    k_fill<<<(EE + 255) / 256, 256>>>(ei);

    const int GB = (NN + 63) / 64;  // 782

    // layer 1: mean-aggregate x, then fused dual GEMM + bias + relu (FFMA2)
    k_agg_mean<<<(NN * 32 + 255) / 256, 256>>>(x, 0);
    k_gemm_relu128<<<GB, 256>>>(x, W1l, W1r, b1l);

    // layer 2: mean-aggregate h1, then fused dual GEMM + bias (FFMA2)
    k_agg_mean<<<(NN * 32 + 255) / 256, 256>>>(x, 1);
    k_gemm_64<<<GB, 256>>>(W2l, W2r, b2l);

    // softmax
    k_softmax<<<(NN * 32 + 255) / 256, 256>>>();

    // GCN: y = (h2 @ Wg) * dinv (FFMA2), then normalized aggregation + bias
    k_gemm_gcn<<<GB, 256>>>(Wg);
    k_gcn_agg<<<(NN * 16 + 255) / 256, 256>>>(bg, out);
}

// round 8
// speedup vs baseline: 1.1066x; 1.1066x over previous
#include <cuda_runtime.h>

#define NN 50000
#define EE 800000
#define SB 256
#define NBLK ((NN + SB - 1) / SB)   // 196

// ---------------- device scratch (static only) ----------------
__device__ int    d_is64;
__device__ int    d_cnt[NN];
__device__ int    d_cursor[NN];
__device__ int    d_rowptr[NN + 1];
__device__ int    d_col[EE];
__device__ int    d_bsum[SB];
__device__ float4 d_t1l[NN * 32];  // [NN,128] = x @ W1l   (gathered)
__device__ float4 d_t1r[NN * 32];  // [NN,128] = x @ W1r   (self)
__device__ float4 d_h1[NN * 32];   // [NN,128]
__device__ float4 d_t2l[NN * 16];  // [NN,64]  = h1 @ W2l  (gathered)
__device__ float4 d_t2r[NN * 16];  // [NN,64]  = h1 @ W2r  (self)
__device__ float4 d_h2[NN * 16];   // [NN,64]  softmax output
__device__ float4 d_y[NN * 16];    // [NN,64]  (h2@Wg)*dinv

// ---------------- init: zero counters + edge-dtype probe (fused) ----------------
__global__ void k_init(const int* __restrict__ ei) {
    int i = blockIdx.x * blockDim.x + threadIdx.x;
    if (i < NN) { d_cnt[i] = 0; d_cursor[i] = 0; }
    if (blockIdx.x == 0) {
        __shared__ int nonzero;
        if (threadIdx.x == 0) nonzero = 0;
        __syncthreads();
        for (int j = threadIdx.x; j < 4096; j += blockDim.x)
            if (ei[2 * j + 1] != 0) nonzero = 1;
        __syncthreads();
        if (threadIdx.x == 0) d_is64 = (nonzero == 0) ? 1 : 0;
    }
}

__device__ __forceinline__ int edge_id(const void* ei, int which, int e) {
    if (d_is64) return (int)((const long long*)ei)[(size_t)which * EE + e];
    return ((const int*)ei)[(size_t)which * EE + e];
}

// ---------------- CSR build ----------------
__global__ void k_count(const void* __restrict__ ei) {
    int e = blockIdx.x * blockDim.x + threadIdx.x;
    if (e < EE) atomicAdd(&d_cnt[edge_id(ei, 1, e)], 1);
}

__global__ void k_scan1() {
    __shared__ int s[SB];
    int tid = threadIdx.x;
    int i = blockIdx.x * SB + tid;
    int v = (i < NN) ? d_cnt[i] : 0;
    s[tid] = v;
    __syncthreads();
    for (int off = 1; off < SB; off <<= 1) {
        int t = (tid >= off) ? s[tid - off] : 0;
        __syncthreads();
        s[tid] += t;
        __syncthreads();
    }
    if (i < NN) d_rowptr[i] = s[tid] - v;            // exclusive within block
    if (tid == SB - 1) d_bsum[blockIdx.x] = s[tid];  // block total
}

// scan of block sums + apply offset, fused (each block redundantly scans 196 sums)
__global__ void k_scan23() {
    __shared__ int s[SB];
    int tid = threadIdx.x;
    s[tid] = (tid < NBLK) ? d_bsum[tid] : 0;
    __syncthreads();
    for (int off = 1; off < SB; off <<= 1) {
        int t = (tid >= off) ? s[tid - off] : 0;
        __syncthreads();
        s[tid] += t;
        __syncthreads();
    }
    int prefix = (blockIdx.x == 0) ? 0 : s[blockIdx.x - 1];
    int i = blockIdx.x * SB + tid;
    if (i < NN) d_rowptr[i] += prefix;
    if (i == 0) d_rowptr[NN] = EE;
}

__global__ void k_fill(const void* __restrict__ ei) {
    int e = blockIdx.x * blockDim.x + threadIdx.x;
    if (e < EE) {
        int d = edge_id(ei, 1, e);
        int s = edge_id(ei, 0, e);
        int p = atomicAdd(&d_cursor[d], 1);
        d_col[d_rowptr[d] + p] = s;
    }
}

// ------------- layer1 GEMM: [t1l|t1r] = x @ [W1l|W1r]; M=NN, N=256, K=128 -----------------
// BM=64, BN=256, 256 threads, micro-tile 8 rows x 8 cols (two float4 col groups).
__global__ void __launch_bounds__(256) k_gemm_l1(
    const float* __restrict__ x,
    const float* __restrict__ W1, const float* __restrict__ W2)
{
    __shared__ float As[64][17];
    __shared__ float Ws[16][256];
    int tid = threadIdx.x;
    int rowBase = blockIdx.x * 64;
    int rg = tid >> 5;   // 0..7  -> rows rg*8..+7
    int cg = tid & 31;   // 0..31 -> cols cg*4 (left half) and 128+cg*4 (right half)
    float acc[8][8];
#pragma unroll
    for (int i = 0; i < 8; i++)
#pragma unroll
        for (int j = 0; j < 8; j++) acc[i][j] = 0.f;

    int lr = tid >> 2;          // 0..63
    int lc = (tid & 3) * 4;     // 0,4,8,12
    bool lvalid = (rowBase + lr) < NN;

    for (int kk = 0; kk < 128; kk += 16) {
        float4 va = make_float4(0.f, 0.f, 0.f, 0.f);
        if (lvalid) va = *(const float4*)(x + (size_t)(rowBase + lr) * 128 + kk + lc);
        As[lr][lc + 0] = va.x; As[lr][lc + 1] = va.y;
        As[lr][lc + 2] = va.z; As[lr][lc + 3] = va.w;
        // Ws: 16 rows x 256 cols = 1024 float4, 4 per thread
#pragma unroll
        for (int it = 0; it < 4; it++) {
            int idx = tid + it * 256;
            int wr = idx >> 6;          // 0..15
            int c4 = idx & 63;          // 0..63 (float4 col)
            int col = c4 * 4;
            const float* src = (col < 128)
                ? (W1 + (size_t)(kk + wr) * 128 + col)
                : (W2 + (size_t)(kk + wr) * 128 + (col - 128));
            *(float4*)&Ws[wr][col] = *(const float4*)src;
        }
        __syncthreads();
#pragma unroll
        for (int k = 0; k < 16; k++) {
            float4 b0 = *(const float4*)&Ws[k][cg * 4];
            float4 b1 = *(const float4*)&Ws[k][128 + cg * 4];
#pragma unroll
            for (int i = 0; i < 8; i++) {
                float a = As[rg * 8 + i][k];
                acc[i][0] += a * b0.x; acc[i][1] += a * b0.y;
                acc[i][2] += a * b0.z; acc[i][3] += a * b0.w;
                acc[i][4] += a * b1.x; acc[i][5] += a * b1.y;
                acc[i][6] += a * b1.z; acc[i][7] += a * b1.w;
            }
        }
        __syncthreads();
    }
#pragma unroll
    for (int i = 0; i < 8; i++) {
        int r = rowBase + rg * 8 + i;
        if (r < NN) {
            d_t1l[(size_t)r * 32 + cg] = make_float4(acc[i][0], acc[i][1], acc[i][2], acc[i][3]);
            d_t1r[(size_t)r * 32 + cg] = make_float4(acc[i][4], acc[i][5], acc[i][6], acc[i][7]);
        }
    }
}

// ---------- layer1 agg: h1 = relu(mean_nbr(t1l) + t1r[self] + b1l); warp per node ---------
__global__ void k_agg1(const float* __restrict__ b1l) {
    int idx = blockIdx.x * blockDim.x + threadIdx.x;
    int node = idx >> 5;
    int lane = idx & 31;
    if (node >= NN) return;
    int beg = d_rowptr[node], end = d_rowptr[node + 1];
    float4 acc = make_float4(0.f, 0.f, 0.f, 0.f);
    for (int j = beg; j < end; j++) {
        int s = d_col[j];
        float4 v = d_t1l[(size_t)s * 32 + lane];
        acc.x += v.x; acc.y += v.y; acc.z += v.z; acc.w += v.w;
    }
    int c = end - beg;
    float inv = 1.0f / (float)(c > 0 ? c : 1);
    float4 self = d_t1r[(size_t)node * 32 + lane];
    float4 b = ((const float4*)b1l)[lane];
    float4 o;
    o.x = fmaxf(acc.x * inv + self.x + b.x, 0.f);
    o.y = fmaxf(acc.y * inv + self.y + b.y, 0.f);
    o.z = fmaxf(acc.z * inv + self.z + b.z, 0.f);
    o.w = fmaxf(acc.w * inv + self.w + b.w, 0.f);
    d_h1[(size_t)node * 32 + lane] = o;
}

// ------------- layer2 GEMM: [t2l|t2r] = h1 @ [W2l|W2r]; M=NN, N=128, K=128 ----------------
// BM=64, BN=128, 256 threads, micro-tile 8 rows x 4 cols.
__global__ void __launch_bounds__(256) k_gemm_l2(
    const float* __restrict__ W1, const float* __restrict__ W2)
{
    __shared__ float As[64][17];
    __shared__ float Ws[16][128];
    int tid = threadIdx.x;
    int rowBase = blockIdx.x * 64;
    int rg = tid >> 5;   // 0..7
    int cg = tid & 31;   // cols cg*4 (0..127)
    float acc[8][4];
#pragma unroll
    for (int i = 0; i < 8; i++)
#pragma unroll
        for (int j = 0; j < 4; j++) acc[i][j] = 0.f;

    int lr = tid >> 2;
    int lc = (tid & 3) * 4;
    bool lvalid = (rowBase + lr) < NN;
    const float* A = (const float*)d_h1;

    for (int kk = 0; kk < 128; kk += 16) {
        float4 va = make_float4(0.f, 0.f, 0.f, 0.f);
        if (lvalid) va = *(const float4*)(A + (size_t)(rowBase + lr) * 128 + kk + lc);
        As[lr][lc + 0] = va.x; As[lr][lc + 1] = va.y;
        As[lr][lc + 2] = va.z; As[lr][lc + 3] = va.w;
#pragma unroll
        for (int it = 0; it < 2; it++) {
            int idx = tid + it * 256;
            int wr = idx >> 5;          // 0..15
            int c4 = idx & 31;          // 0..31
            int col = c4 * 4;
            const float* src = (col < 64)
                ? (W1 + (size_t)(kk + wr) * 64 + col)
                : (W2 + (size_t)(kk + wr) * 64 + (col - 64));
            *(float4*)&Ws[wr][col] = *(const float4*)src;
        }
        __syncthreads();
#pragma unroll
        for (int k = 0; k < 16; k++) {
            float4 bv = *(const float4*)&Ws[k][cg * 4];
#pragma unroll
            for (int i = 0; i < 8; i++) {
                float a = As[rg * 8 + i][k];
                acc[i][0] += a * bv.x;
                acc[i][1] += a * bv.y;
                acc[i][2] += a * bv.z;
                acc[i][3] += a * bv.w;
            }
        }
        __syncthreads();
    }
#pragma unroll
    for (int i = 0; i < 8; i++) {
        int r = rowBase + rg * 8 + i;
        if (r < NN) {
            float4 v = make_float4(acc[i][0], acc[i][1], acc[i][2], acc[i][3]);
            if (cg < 16) d_t2l[(size_t)r * 16 + cg] = v;
            else         d_t2r[(size_t)r * 16 + (cg - 16)] = v;
        }
    }
}

// ------- layer2 agg + bias + softmax: h2 = softmax(mean_nbr(t2l) + t2r[self] + b2l) -------
__global__ void k_agg2sm(const float* __restrict__ b2l) {
    int idx = blockIdx.x * blockDim.x + threadIdx.x;
    int node = idx >> 5;
    int lane = idx & 31;
    if (node >= NN) return;
    int beg = d_rowptr[node], end = d_rowptr[node + 1];
    const float2* t2 = (const float2*)d_t2l;   // row = 32 float2
    float ax = 0.f, ay = 0.f;
    for (int j = beg; j < end; j++) {
        int s = d_col[j];
        float2 v = t2[(size_t)s * 32 + lane];
        ax += v.x; ay += v.y;
    }
    int c = end - beg;
    float inv = 1.0f / (float)(c > 0 ? c : 1);
    float2 self = ((const float2*)d_t2r)[(size_t)node * 32 + lane];
    float2 b = ((const float2*)b2l)[lane];
    float vx = ax * inv + self.x + b.x;
    float vy = ay * inv + self.y + b.y;
    float m = fmaxf(vx, vy);
    for (int o = 16; o > 0; o >>= 1) m = fmaxf(m, __shfl_xor_sync(0xffffffffu, m, o));
    float ex = __expf(vx - m), ey = __expf(vy - m);
    float s = ex + ey;
    for (int o = 16; o > 0; o >>= 1) s += __shfl_xor_sync(0xffffffffu, s, o);
    float is = 1.0f / s;
    ((float2*)d_h2)[(size_t)node * 32 + lane] = make_float2(ex * is, ey * is);
}

// ---------------- GCN GEMM: y = (h2 @ Wg) * dinv[row]; M=NN, N=64, K=64 -------------------
__global__ void __launch_bounds__(256) k_gemm_gcn(const float* __restrict__ Wg) {
    __shared__ float As[64][17];
    __shared__ float Ws[16][64];
    int tid = threadIdx.x;
    int rowBase = blockIdx.x * 64;
    int rg = tid >> 4;   // 0..15 -> rows rg*4..+3
    int cg = tid & 15;   // cols cg*4..+3
    float acc[4][4];
#pragma unroll
    for (int i = 0; i < 4; i++)
#pragma unroll
        for (int j = 0; j < 4; j++) acc[i][j] = 0.f;

    int lr = tid >> 2;
    int lc = (tid & 3) * 4;
    bool lvalid = (rowBase + lr) < NN;
    const float* A = (const float*)d_h2;

    for (int kk = 0; kk < 64; kk += 16) {
        float4 va = make_float4(0.f, 0.f, 0.f, 0.f);
        if (lvalid) va = *(const float4*)(A + (size_t)(rowBase + lr) * 64 + kk + lc);
        As[lr][lc + 0] = va.x; As[lr][lc + 1] = va.y;
        As[lr][lc + 2] = va.z; As[lr][lc + 3] = va.w;
        {
            int wr = tid >> 4;
            int wc = (tid & 15) * 4;
            *(float4*)&Ws[wr][wc] = *(const float4*)(Wg + (size_t)(kk + wr) * 64 + wc);
        }
        __syncthreads();
#pragma unroll
        for (int k = 0; k < 16; k++) {
            float4 bv = *(const float4*)&Ws[k][cg * 4];
#pragma unroll
            for (int i = 0; i < 4; i++) {
                float a = As[rg * 4 + i][k];
                acc[i][0] += a * bv.x;
                acc[i][1] += a * bv.y;
                acc[i][2] += a * bv.z;
                acc[i][3] += a * bv.w;
            }
        }
        __syncthreads();
    }
#pragma unroll
    for (int i = 0; i < 4; i++) {
        int r = rowBase + rg * 4 + i;
        if (r < NN) {
            float dinv = rsqrtf((float)(d_cnt[r] + 1));
            float4 v = make_float4(acc[i][0] * dinv, acc[i][1] * dinv,
                                   acc[i][2] * dinv, acc[i][3] * dinv);
            d_y[(size_t)r * 16 + cg] = v;
        }
    }
}

// ---------------- GCN aggregation: out[i] = dinv[i]*(y[i] + sum_nbr y[j]) + bg ------------
__global__ void k_gcn_agg(const float* __restrict__ bg, float* __restrict__ out) {
    int idx = blockIdx.x * blockDim.x + threadIdx.x;
    int node = idx >> 4;
    int lane = idx & 15;
    if (node >= NN) return;
    float4 acc = d_y[(size_t)node * 16 + lane];  // self loop
    int beg = d_rowptr[node], end = d_rowptr[node + 1];
    for (int j = beg; j < end; j++) {
        int s = d_col[j];
        float4 v = d_y[(size_t)s * 16 + lane];
        acc.x += v.x; acc.y += v.y; acc.z += v.z; acc.w += v.w;
    }
    float dinv = rsqrtf((float)(d_cnt[node] + 1));
    float4 b = ((const float4*)bg)[lane];
    float4 o;
    o.x = acc.x * dinv + b.x;
    o.y = acc.y * dinv + b.y;
    o.z = acc.z * dinv + b.z;
    o.w = acc.w * dinv + b.w;
    ((float4*)out)[(size_t)node * 16 + lane] = o;
}

// ---------------- launch ----------------
extern "C" void kernel_launch(void* const* d_in, const int* in_sizes, int n_in,
                              void* d_out, int out_size) {
    const float* x = (const float*)d_in[0];
    const void* ei = d_in[1];
    const float* W1l = (const float*)d_in[2];
    const float* b1l = (const float*)d_in[3];
    const float* W1r = (const float*)d_in[4];
    const float* W2l = (const float*)d_in[5];
    const float* b2l = (const float*)d_in[6];
    const float* W2r = (const float*)d_in[7];
    const float* Wg  = (const float*)d_in[8];
    const float* bg  = (const float*)d_in[9];
    float* out = (float*)d_out;

    // init (zero + dtype probe) + CSR build: 5 launches
    k_init<<<(NN + 255) / 256, 256>>>((const int*)ei);
    k_count<<<(EE + 255) / 256, 256>>>(ei);
    k_scan1<<<NBLK, SB>>>();
    k_scan23<<<NBLK, SB>>>();
    k_fill<<<(EE + 255) / 256, 256>>>(ei);

    const int GB = (NN + 63) / 64;  // 782

    // layer 1: GEMM first (aggregation is linear), then fused agg+bias+relu
    k_gemm_l1<<<GB, 256>>>(x, W1l, W1r);
    k_agg1<<<(NN * 32 + 255) / 256, 256>>>(b1l);

    // layer 2: dual GEMM, then fused agg+bias+softmax (64-feature gather)
    k_gemm_l2<<<GB, 256>>>(W2l, W2r);
    k_agg2sm<<<(NN * 32 + 255) / 256, 256>>>(b2l);

    // GCN: y = (h2 @ Wg) * dinv, then normalized aggregation + bias
    k_gemm_gcn<<<GB, 256>>>(Wg);
    k_gcn_agg<<<(NN * 16 + 255) / 256, 256>>>(bg, out);
}

// round 10
// speedup vs baseline: 1.4138x; 1.2776x over previous
#include <cuda_runtime.h>

#define NN 50000
#define EE 800000
#define SB 256
#define NBLK ((NN + SB - 1) / SB)   // 196
#define TS 40                       // smem tile row stride (bf16 elems), 32 data + 8 pad

typedef unsigned long long ull;

// ---------------- device scratch (static only) ----------------
__device__ int    d_is64;
__device__ int    d_cnt[NN];
__device__ int    d_cursor[NN];
__device__ int    d_rowptr[NN + 1];
__device__ int    d_col[EE];
__device__ int    d_bsum[SB];
__device__ float4 d_t1l[NN * 32];  // [NN,128] = x @ W1l   (gathered)
__device__ float4 d_t1r[NN * 32];  // [NN,128] = x @ W1r   (self)
__device__ float4 d_h1[NN * 32];   // [NN,128]
__device__ float4 d_t2l[NN * 16];  // [NN,64]  = h1 @ W2l  (gathered)
__device__ float4 d_t2r[NN * 16];  // [NN,64]  = h1 @ W2r  (self)
__device__ float4 d_h2[NN * 16];   // [NN,64]  softmax output
__device__ float4 d_y[NN * 16];    // [NN,64]  (h2@Wg)*dinv
// transposed bf16-split weights: WT[n][k] = W[k][n]
__device__ uint4  d_wt1h4[256 * 128 / 8];   // [256,128] bf16 hi
__device__ uint4  d_wt1lo4[256 * 128 / 8];  // [256,128] bf16 lo
__device__ uint4  d_wt2h4[128 * 128 / 8];   // [128,128] bf16 hi
__device__ uint4  d_wt2lo4[128 * 128 / 8];  // [128,128] bf16 lo

// ---------------- helpers ----------------
__device__ __forceinline__ unsigned short bf16rne(float f) {
    unsigned u = __float_as_uint(f);
    unsigned r = u + 0x7FFFu + ((u >> 16) & 1u);
    return (unsigned short)(r >> 16);
}
__device__ __forceinline__ float bf16tof(unsigned short h) {
    return __uint_as_float((unsigned)h << 16);
}
__device__ __forceinline__ unsigned smem_u32(const void* p) {
    unsigned a;
    asm("{ .reg .u64 t; cvta.to.shared.u64 t, %1; cvt.u32.u64 %0, t; }" : "=r"(a) : "l"(p));
    return a;
}
__device__ __forceinline__ void ldm_x4(unsigned (&r)[4], unsigned addr) {
    asm volatile("ldmatrix.sync.aligned.m8n8.x4.shared.b16 {%0,%1,%2,%3}, [%4];"
                 : "=r"(r[0]), "=r"(r[1]), "=r"(r[2]), "=r"(r[3]) : "r"(addr));
}
__device__ __forceinline__ void mma16816(float (&d)[4], const unsigned (&a)[4],
                                         unsigned b0, unsigned b1) {
    asm volatile(
        "mma.sync.aligned.m16n8k16.row.col.f32.bf16.bf16.f32 "
        "{%0,%1,%2,%3}, {%4,%5,%6,%7}, {%8,%9}, {%0,%1,%2,%3};"
        : "+f"(d[0]), "+f"(d[1]), "+f"(d[2]), "+f"(d[3])
        : "r"(a[0]), "r"(a[1]), "r"(a[2]), "r"(a[3]), "r"(b0), "r"(b1));
}

// ---------------- init: zero counters + edge-dtype probe (fused) ----------------
__global__ void k_init(const int* __restrict__ ei) {
    int i = blockIdx.x * blockDim.x + threadIdx.x;
    if (i < NN) { d_cnt[i] = 0; d_cursor[i] = 0; }
    if (blockIdx.x == 0) {
        __shared__ int nonzero;
        if (threadIdx.x == 0) nonzero = 0;
        __syncthreads();
        for (int j = threadIdx.x; j < 4096; j += blockDim.x)
            if (ei[2 * j + 1] != 0) nonzero = 1;
        __syncthreads();
        if (threadIdx.x == 0) d_is64 = (nonzero == 0) ? 1 : 0;
    }
}

__device__ __forceinline__ int edge_id(const void* ei, int which, int e) {
    if (d_is64) return (int)((const long long*)ei)[(size_t)which * EE + e];
    return ((const int*)ei)[(size_t)which * EE + e];
}

// ---------------- CSR build ----------------
__global__ void k_count(const void* __restrict__ ei) {
    int e = blockIdx.x * blockDim.x + threadIdx.x;
    if (e < EE) atomicAdd(&d_cnt[edge_id(ei, 1, e)], 1);
}

__global__ void k_scan1() {
    __shared__ int s[SB];
    int tid = threadIdx.x;
    int i = blockIdx.x * SB + tid;
    int v = (i < NN) ? d_cnt[i] : 0;
    s[tid] = v;
    __syncthreads();
    for (int off = 1; off < SB; off <<= 1) {
        int t = (tid >= off) ? s[tid - off] : 0;
        __syncthreads();
        s[tid] += t;
        __syncthreads();
    }
    if (i < NN) d_rowptr[i] = s[tid] - v;
    if (tid == SB - 1) d_bsum[blockIdx.x] = s[tid];
}

__global__ void k_scan23() {
    __shared__ int s[SB];
    int tid = threadIdx.x;
    s[tid] = (tid < NBLK) ? d_bsum[tid] : 0;
    __syncthreads();
    for (int off = 1; off < SB; off <<= 1) {
        int t = (tid >= off) ? s[tid - off] : 0;
        __syncthreads();
        s[tid] += t;
        __syncthreads();
    }
    int prefix = (blockIdx.x == 0) ? 0 : s[blockIdx.x - 1];
    int i = blockIdx.x * SB + tid;
    if (i < NN) d_rowptr[i] += prefix;
    if (i == 0) d_rowptr[NN] = EE;
}

__global__ void k_fill(const void* __restrict__ ei) {
    int e = blockIdx.x * blockDim.x + threadIdx.x;
    if (e < EE) {
        int d = edge_id(ei, 1, e);
        int s = edge_id(ei, 0, e);
        int p = atomicAdd(&d_cursor[d], 1);
        d_col[d_rowptr[d] + p] = s;
    }
}

// -------- weight prep: transpose + bf16 hi/lo split (WT[n][k] = W[k][n]) ---------
__global__ void k_prep_w(const float* __restrict__ W1l, const float* __restrict__ W1r,
                         const float* __restrict__ W2l, const float* __restrict__ W2r) {
    int idx = blockIdx.x * blockDim.x + threadIdx.x;
    if (idx < 256 * 128) {
        int n = idx >> 7, k = idx & 127;
        float w = (n < 128) ? W1l[k * 128 + n] : W1r[k * 128 + (n - 128)];
        unsigned short h = bf16rne(w);
        ((unsigned short*)d_wt1h4)[idx] = h;
        ((unsigned short*)d_wt1lo4)[idx] = bf16rne(w - bf16tof(h));
    }
    if (idx < 128 * 128) {
        int n = idx >> 7, k = idx & 127;
        float w = (n < 64) ? W2l[k * 64 + n] : W2r[k * 64 + (n - 64)];
        unsigned short h = bf16rne(w);
        ((unsigned short*)d_wt2h4)[idx] = h;
        ((unsigned short*)d_wt2lo4)[idx] = bf16rne(w - bf16tof(h));
    }
}

// ---------------- mma.sync bf16-split GEMM ----------------
// which==0 (layer1): D[NN,256] = x @ [W1l|W1r]; blockIdx.y=0 -> t1l, =1 -> t1r
// which==1 (layer2): D[NN,128] = h1 @ [W2l|W2r]; cols<64 -> t2l, else t2r
// A = A_hi + A_lo (bf16), W = W_hi + W_lo; acc = Ah*Wh + Al*Wh + Ah*Wl (fp32).
// Block 128x128, 8 warps, warp tile 64x32 (4x4 m16n8 subtiles).
__global__ void __launch_bounds__(256) k_gemm_mma(const float* __restrict__ Aext, int which) {
    __shared__ __align__(16) unsigned short sAh[128 * TS];
    __shared__ __align__(16) unsigned short sAl[128 * TS];
    __shared__ __align__(16) unsigned short sBh[128 * TS];
    __shared__ __align__(16) unsigned short sBl[128 * TS];

    const float* A = which ? (const float*)d_h1 : Aext;
    const unsigned short* WTh = which ? (const unsigned short*)d_wt2h4
                                      : (const unsigned short*)d_wt1h4;
    const unsigned short* WTl = which ? (const unsigned short*)d_wt2lo4
                                      : (const unsigned short*)d_wt1lo4;
    int tid = threadIdx.x;
    int wid = tid >> 5;
    int lane = tid & 31;
    int wm = wid >> 2;          // 0..1 -> m offset wm*64
    int wn = wid & 3;           // 0..3 -> n offset wn*32
    int rowBase = blockIdx.x * 128;
    int nBase = blockIdx.y * 128;

    float acc[4][4][4];
#pragma unroll
    for (int mi = 0; mi < 4; mi++)
#pragma unroll
        for (int ni = 0; ni < 4; ni++)
#pragma unroll
            for (int q = 0; q < 4; q++) acc[mi][ni][q] = 0.f;

    unsigned bAh = smem_u32(sAh), bAl = smem_u32(sAl);
    unsigned bBh = smem_u32(sBh), bBl = smem_u32(sBl);

    int frow = tid >> 1;            // 0..127
    int fcol = (tid & 1) * 16;      // 0 or 16
    int grow = rowBase + frow;

    for (int kk = 0; kk < 128; kk += 32) {
        // ---- A tile: rows 0..127, k in [kk, kk+32); fp32 -> bf16 hi/lo ----
        {
            float t[16];
            if (grow < NN) {
                const float4* src = (const float4*)(A + (size_t)grow * 128 + kk + fcol);
#pragma unroll
                for (int i = 0; i < 4; i++) {
                    float4 v = src[i];
                    t[i * 4 + 0] = v.x; t[i * 4 + 1] = v.y;
                    t[i * 4 + 2] = v.z; t[i * 4 + 3] = v.w;
                }
            } else {
#pragma unroll
                for (int i = 0; i < 16; i++) t[i] = 0.f;
            }
            unsigned short hb[16], lb[16];
#pragma unroll
            for (int i = 0; i < 16; i++) {
                hb[i] = bf16rne(t[i]);
                lb[i] = bf16rne(t[i] - bf16tof(hb[i]));
            }
            uint4* dh = (uint4*)&sAh[frow * TS + fcol];
            uint4* dl = (uint4*)&sAl[frow * TS + fcol];
            dh[0] = ((uint4*)hb)[0]; dh[1] = ((uint4*)hb)[1];
            dl[0] = ((uint4*)lb)[0]; dl[1] = ((uint4*)lb)[1];
        }
        // ---- B tile: WT rows nBase..+127, k in [kk, kk+32); straight bf16 copy ----
        {
            const uint4* sh = (const uint4*)(WTh + (size_t)(nBase + frow) * 128 + kk + fcol);
            const uint4* sl = (const uint4*)(WTl + (size_t)(nBase + frow) * 128 + kk + fcol);
            uint4* dh = (uint4*)&sBh[frow * TS + fcol];
            uint4* dl = (uint4*)&sBl[frow * TS + fcol];
            dh[0] = sh[0]; dh[1] = sh[1];
            dl[0] = sl[0]; dl[1] = sl[1];
        }
        __syncthreads();

#pragma unroll
        for (int ks = 0; ks < 32; ks += 16) {
            // A fragments (hi & lo) for 4 m-subtiles
            unsigned aH[4][4], aL[4][4];
#pragma unroll
            for (int mi = 0; mi < 4; mi++) {
                int row = wm * 64 + mi * 16 + (lane & 15);
                int col = ks + (lane >> 4) * 8;
                unsigned off = (unsigned)(row * TS + col) * 2;
                ldm_x4(aH[mi], bAh + off);
                ldm_x4(aL[mi], bAl + off);
            }
            // B fragments (hi & lo) for 4 n-subtiles (two per ldmatrix.x4)
            unsigned bH[4][2], bL[4][2];
#pragma unroll
            for (int nip = 0; nip < 4; nip += 2) {
                int nrow = wn * 32 + nip * 8 + ((lane >> 4) & 1) * 8 + (lane & 7);
                int kcol = ks + ((lane >> 3) & 1) * 8;
                unsigned off = (unsigned)(nrow * TS + kcol) * 2;
                unsigned r[4];
                ldm_x4(r, bBh + off);
                bH[nip][0] = r[0]; bH[nip][1] = r[1];
                bH[nip + 1][0] = r[2]; bH[nip + 1][1] = r[3];
                ldm_x4(r, bBl + off);
                bL[nip][0] = r[0]; bL[nip][1] = r[1];
                bL[nip + 1][0] = r[2]; bL[nip + 1][1] = r[3];
            }
            // 3 products: hi*hi + lo*hi + hi*lo
#pragma unroll
            for (int mi = 0; mi < 4; mi++)
#pragma unroll
                for (int ni = 0; ni < 4; ni++) {
                    mma16816(acc[mi][ni], aH[mi], bH[ni][0], bH[ni][1]);
                    mma16816(acc[mi][ni], aL[mi], bH[ni][0], bH[ni][1]);
                    mma16816(acc[mi][ni], aH[mi], bL[ni][0], bL[ni][1]);
                }
        }
        __syncthreads();
    }

    // ---- epilogue: registers -> global fp32 ----
    float* outL = which ? (float*)d_t2l : (float*)d_t1l;
    float* outR = which ? (float*)d_t2r : (float*)d_t1r;
#pragma unroll
    for (int mi = 0; mi < 4; mi++) {
        int r0 = rowBase + wm * 64 + mi * 16 + (lane >> 2);
#pragma unroll
        for (int ni = 0; ni < 4; ni++) {
            int cl = wn * 32 + ni * 8 + (lane & 3) * 2;   // 0..127 within block cols
            float* dst;
            if (!which) {
                dst = (blockIdx.y == 0) ? (outL + (size_t)0) : (outR + (size_t)0);
                if (r0 < NN)
                    *(float2*)(dst + (size_t)r0 * 128 + cl) =
                        make_float2(acc[mi][ni][0], acc[mi][ni][1]);
                if (r0 + 8 < NN)
                    *(float2*)(dst + (size_t)(r0 + 8) * 128 + cl) =
                        make_float2(acc[mi][ni][2], acc[mi][ni][3]);
            } else {
                int c = cl;
                float* base = (c < 64) ? (outL + c) : (outR + (c - 64));
                if (r0 < NN)
                    *(float2*)(base + (size_t)r0 * 64) =
                        make_float2(acc[mi][ni][0], acc[mi][ni][1]);
                if (r0 + 8 < NN)
                    *(float2*)(base + (size_t)(r0 + 8) * 64) =
                        make_float2(acc[mi][ni][2], acc[mi][ni][3]);
            }
        }
    }
}

// ---------- layer1 agg: h1 = relu(mean_nbr(t1l) + t1r[self] + b1l); warp per node ---------
__global__ void k_agg1(const float* __restrict__ b1l) {
    int idx = blockIdx.x * blockDim.x + threadIdx.x;
    int node = idx >> 5;
    int lane = idx & 31;
    if (node >= NN) return;
    int beg = d_rowptr[node], end = d_rowptr[node + 1];
    float4 acc = make_float4(0.f, 0.f, 0.f, 0.f);
    for (int j = beg; j < end; j++) {
        int s = d_col[j];
        float4 v = d_t1l[(size_t)s * 32 + lane];
        acc.x += v.x; acc.y += v.y; acc.z += v.z; acc.w += v.w;
    }
    int c = end - beg;
    float inv = 1.0f / (float)(c > 0 ? c : 1);
    float4 self = d_t1r[(size_t)node * 32 + lane];
    float4 b = ((const float4*)b1l)[lane];
    float4 o;
    o.x = fmaxf(acc.x * inv + self.x + b.x, 0.f);
    o.y = fmaxf(acc.y * inv + self.y + b.y, 0.f);
    o.z = fmaxf(acc.z * inv + self.z + b.z, 0.f);
    o.w = fmaxf(acc.w * inv + self.w + b.w, 0.f);
    d_h1[(size_t)node * 32 + lane] = o;
}

// ------- layer2 agg + bias + softmax: h2 = softmax(mean_nbr(t2l) + t2r[self] + b2l) -------
__global__ void k_agg2sm(const float* __restrict__ b2l) {
    int idx = blockIdx.x * blockDim.x + threadIdx.x;
    int node = idx >> 5;
    int lane = idx & 31;
    if (node >= NN) return;
    int beg = d_rowptr[node], end = d_rowptr[node + 1];
    const float2* t2 = (const float2*)d_t2l;
    float ax = 0.f, ay = 0.f;
    for (int j = beg; j < end; j++) {
        int s = d_col[j];
        float2 v = t2[(size_t)s * 32 + lane];
        ax += v.x; ay += v.y;
    }
    int c = end - beg;
    float inv = 1.0f / (float)(c > 0 ? c : 1);
    float2 self = ((const float2*)d_t2r)[(size_t)node * 32 + lane];
    float2 b = ((const float2*)b2l)[lane];
    float vx = ax * inv + self.x + b.x;
    float vy = ay * inv + self.y + b.y;
    float m = fmaxf(vx, vy);
    for (int o = 16; o > 0; o >>= 1) m = fmaxf(m, __shfl_xor_sync(0xffffffffu, m, o));
    float ex = __expf(vx - m), ey = __expf(vy - m);
    float s = ex + ey;
    for (int o = 16; o > 0; o >>= 1) s += __shfl_xor_sync(0xffffffffu, s, o);
    float is = 1.0f / s;
    ((float2*)d_h2)[(size_t)node * 32 + lane] = make_float2(ex * is, ey * is);
}

// ---------------- GCN GEMM (FFMA): y = (h2 @ Wg) * dinv[row]; M=NN, N=64, K=64 ------------
__global__ void __launch_bounds__(256) k_gemm_gcn(const float* __restrict__ Wg) {
    __shared__ float As[64][17];
    __shared__ float Ws[16][64];
    int tid = threadIdx.x;
    int rowBase = blockIdx.x * 64;
    int rg = tid >> 4;
    int cg = tid & 15;
    float acc[4][4];
#pragma unroll
    for (int i = 0; i < 4; i++)
#pragma unroll
        for (int j = 0; j < 4; j++) acc[i][j] = 0.f;

    int lr = tid >> 2;
    int lc = (tid & 3) * 4;
    bool lvalid = (rowBase + lr) < NN;
    const float* A = (const float*)d_h2;

    for (int kk = 0; kk < 64; kk += 16) {
        float4 va = make_float4(0.f, 0.f, 0.f, 0.f);
        if (lvalid) va = *(const float4*)(A + (size_t)(rowBase + lr) * 64 + kk + lc);
        As[lr][lc + 0] = va.x; As[lr][lc + 1] = va.y;
        As[lr][lc + 2] = va.z; As[lr][lc + 3] = va.w;
        {
            int wr = tid >> 4;
            int wc = (tid & 15) * 4;
            *(float4*)&Ws[wr][wc] = *(const float4*)(Wg + (size_t)(kk + wr) * 64 + wc);
        }
        __syncthreads();
#pragma unroll
        for (int k = 0; k < 16; k++) {
            float4 bv = *(const float4*)&Ws[k][cg * 4];
#pragma unroll
            for (int i = 0; i < 4; i++) {
                float a = As[rg * 4 + i][k];
                acc[i][0] += a * bv.x;
                acc[i][1] += a * bv.y;
                acc[i][2] += a * bv.z;
                acc[i][3] += a * bv.w;
            }
        }
        __syncthreads();
    }
#pragma unroll
    for (int i = 0; i < 4; i++) {
        int r = rowBase + rg * 4 + i;
        if (r < NN) {
            float dinv = rsqrtf((float)(d_cnt[r] + 1));
            float4 v = make_float4(acc[i][0] * dinv, acc[i][1] * dinv,
                                   acc[i][2] * dinv, acc[i][3] * dinv);
            d_y[(size_t)r * 16 + cg] = v;
        }
    }
}

// ---------------- GCN aggregation: out[i] = dinv[i]*(y[i] + sum_nbr y[j]) + bg ------------
__global__ void k_gcn_agg(const float* __restrict__ bg, float* __restrict__ out) {
    int idx = blockIdx.x * blockDim.x + threadIdx.x;
    int node = idx >> 4;
    int lane = idx & 15;
    if (node >= NN) return;
    float4 acc = d_y[(size_t)node * 16 + lane];
    int beg = d_rowptr[node], end = d_rowptr[node + 1];
    for (int j = beg; j < end; j++) {
        int s = d_col[j];
        float4 v = d_y[(size_t)s * 16 + lane];
        acc.x += v.x; acc.y += v.y; acc.z += v.z; acc.w += v.w;
    }
    float dinv = rsqrtf((float)(d_cnt[node] + 1));
    float4 b = ((const float4*)bg)[lane];
    float4 o;
    o.x = acc.x * dinv + b.x;
    o.y = acc.y * dinv + b.y;
    o.z = acc.z * dinv + b.z;
    o.w = acc.w * dinv + b.w;
    ((float4*)out)[(size_t)node * 16 + lane] = o;
}

// ---------------- launch ----------------
extern "C" void kernel_launch(void* const* d_in, const int* in_sizes, int n_in,
                              void* d_out, int out_size) {
    const float* x = (const float*)d_in[0];
    const void* ei = d_in[1];
    const float* W1l = (const float*)d_in[2];
    const float* b1l = (const float*)d_in[3];
    const float* W1r = (const float*)d_in[4];
    const float* W2l = (const float*)d_in[5];
    const float* b2l = (const float*)d_in[6];
    const float* W2r = (const float*)d_in[7];
    const float* Wg  = (const float*)d_in[8];
    const float* bg  = (const float*)d_in[9];
    float* out = (float*)d_out;

    // init + CSR build + weight prep
    k_init<<<(NN + 255) / 256, 256>>>((const int*)ei);
    k_count<<<(EE + 255) / 256, 256>>>(ei);
    k_scan1<<<NBLK, SB>>>();
    k_scan23<<<NBLK, SB>>>();
    k_fill<<<(EE + 255) / 256, 256>>>(ei);
    k_prep_w<<<128, 256>>>(W1l, W1r, W2l, W2r);

    const int GT = (NN + 127) / 128;  // 391

    // layer 1: mma GEMM (x @ [W1l|W1r], bf16-split), then fused agg+bias+relu
    k_gemm_mma<<<dim3(GT, 2), 256>>>(x, 0);
    k_agg1<<<(NN * 32 + 255) / 256, 256>>>(b1l);

    // layer 2: mma GEMM (h1 @ [W2l|W2r]), then fused agg+bias+softmax
    k_gemm_mma<<<dim3(GT, 1), 256>>>(x, 1);
    k_agg2sm<<<(NN * 32 + 255) / 256, 256>>>(b2l);

    // GCN: y = (h2 @ Wg) * dinv (FFMA), then normalized aggregation + bias
    k_gemm_gcn<<<(NN + 63) / 64, 256>>>(Wg);
    k_gcn_agg<<<(NN * 16 + 255) / 256, 256>>>(bg, out);
}

// round 11
// speedup vs baseline: 1.6162x; 1.1432x over previous
#include <cuda_runtime.h>

#define NN 50000
#define EE 800000
#define CSRB 148                    // CSR-role blocks (== #SMs, wave-1 resident)
#define NSEG 196                    // ceil(NN/256) scan segments
#define TS 40                       // smem tile row stride (bf16 elems), 32 data + 8 pad

typedef unsigned long long ull;

// ---------------- device scratch (static only) ----------------
__device__ int    d_is64;
__device__ int    d_cnt[NN];
__device__ int    d_cursor[NN];
__device__ int    d_rowptr[NN + 1];
__device__ int    d_col[EE];
__device__ int    d_bsum[NSEG];
__device__ unsigned d_gbar[4];      // monotonic epoch barriers (zero-init at load)
__device__ float4 d_t1l[NN * 32];  // [NN,128] = x @ W1l   (gathered)
__device__ float4 d_t1r[NN * 32];  // [NN,128] = x @ W1r   (self)
__device__ float4 d_h1[NN * 32];   // [NN,128]
__device__ float4 d_t2l[NN * 16];  // [NN,64]  = h1 @ W2l  (gathered)
__device__ float4 d_t2r[NN * 16];  // [NN,64]  = h1 @ W2r  (self)
__device__ float4 d_h2[NN * 16];   // [NN,64]  softmax output
__device__ float4 d_y[NN * 16];    // [NN,64]  (h2@Wg)*dinv
// transposed bf16-split weights: WT[n][k] = W[k][n]
__device__ uint4  d_wt1h4[256 * 128 / 8];
__device__ uint4  d_wt1lo4[256 * 128 / 8];
__device__ uint4  d_wt2h4[128 * 128 / 8];
__device__ uint4  d_wt2lo4[128 * 128 / 8];

// ---------------- helpers ----------------
__device__ __forceinline__ unsigned short bf16rne(float f) {
    unsigned u = __float_as_uint(f);
    unsigned r = u + 0x7FFFu + ((u >> 16) & 1u);
    return (unsigned short)(r >> 16);
}
__device__ __forceinline__ float bf16tof(unsigned short h) {
    return __uint_as_float((unsigned)h << 16);
}
__device__ __forceinline__ unsigned smem_u32(const void* p) {
    unsigned a;
    asm("{ .reg .u64 t; cvta.to.shared.u64 t, %1; cvt.u32.u64 %0, t; }" : "=r"(a) : "l"(p));
    return a;
}
__device__ __forceinline__ void ldm_x4(unsigned (&r)[4], unsigned addr) {
    asm volatile("ldmatrix.sync.aligned.m8n8.x4.shared.b16 {%0,%1,%2,%3}, [%4];"
                 : "=r"(r[0]), "=r"(r[1]), "=r"(r[2]), "=r"(r[3]) : "r"(addr));
}
__device__ __forceinline__ void mma16816(float (&d)[4], const unsigned (&a)[4],
                                         unsigned b0, unsigned b1) {
    asm volatile(
        "mma.sync.aligned.m16n8k16.row.col.f32.bf16.bf16.f32 "
        "{%0,%1,%2,%3}, {%4,%5,%6,%7}, {%8,%9}, {%0,%1,%2,%3};"
        : "+f"(d[0]), "+f"(d[1]), "+f"(d[2]), "+f"(d[3])
        : "r"(a[0]), "r"(a[1]), "r"(a[2]), "r"(a[3]), "r"(b0), "r"(b1));
}
// monotonic-epoch grid barrier among the CSRB CSR-role blocks only
__device__ __forceinline__ void grid_bar(int id) {
    __syncthreads();
    if (threadIdx.x == 0) {
        __threadfence();
        unsigned old = atomicAdd(&d_gbar[id], 1u);
        unsigned target = (old / (unsigned)CSRB + 1u) * (unsigned)CSRB;
        unsigned v;
        do {
            asm volatile("ld.global.acquire.gpu.b32 %0, [%1];" : "=r"(v) : "l"(&d_gbar[id]));
        } while (v < target);
    }
    __syncthreads();
}

__device__ __forceinline__ int edge_id(const void* ei, int which, int e) {
    if (d_is64) return (int)((const long long*)ei)[(size_t)which * EE + e];
    return ((const int*)ei)[(size_t)which * EE + e];
}

// -------- weight prep: transpose + bf16 hi/lo split (WT[n][k] = W[k][n]) ---------
__global__ void k_prep_w(const float* __restrict__ W1l, const float* __restrict__ W1r,
                         const float* __restrict__ W2l, const float* __restrict__ W2r) {
    int idx = blockIdx.x * blockDim.x + threadIdx.x;
    if (idx < 256 * 128) {
        int n = idx >> 7, k = idx & 127;
        float w = (n < 128) ? W1l[k * 128 + n] : W1r[k * 128 + (n - 128)];
        unsigned short h = bf16rne(w);
        ((unsigned short*)d_wt1h4)[idx] = h;
        ((unsigned short*)d_wt1lo4)[idx] = bf16rne(w - bf16tof(h));
    }
    if (idx < 128 * 128) {
        int n = idx >> 7, k = idx & 127;
        float w = (n < 64) ? W2l[k * 64 + n] : W2r[k * 64 + (n - 64)];
        unsigned short h = bf16rne(w);
        ((unsigned short*)d_wt2h4)[idx] = h;
        ((unsigned short*)d_wt2lo4)[idx] = bf16rne(w - bf16tof(h));
    }
}

// ---------------- mma.sync bf16-split GEMM body (shared by fused l1 + l2) ----------------
// which==0: D[NN,256] = x @ [W1l|W1r]; nBase=0 -> t1l, 128 -> t1r
// which==1: D[NN,128] = h1 @ [W2l|W2r]; cols<64 -> t2l, else t2r
__device__ __forceinline__ void gemm_body(const float* __restrict__ A,
                                          const unsigned short* __restrict__ WTh,
                                          const unsigned short* __restrict__ WTl,
                                          int which, int rowBase, int nBase) {
    __shared__ __align__(16) unsigned short sAh[128 * TS];
    __shared__ __align__(16) unsigned short sAl[128 * TS];
    __shared__ __align__(16) unsigned short sBh[128 * TS];
    __shared__ __align__(16) unsigned short sBl[128 * TS];

    int tid = threadIdx.x;
    int wid = tid >> 5;
    int lane = tid & 31;
    int wm = wid >> 2;
    int wn = wid & 3;

    float acc[4][4][4];
#pragma unroll
    for (int mi = 0; mi < 4; mi++)
#pragma unroll
        for (int ni = 0; ni < 4; ni++)
#pragma unroll
            for (int q = 0; q < 4; q++) acc[mi][ni][q] = 0.f;

    unsigned bAh = smem_u32(sAh), bAl = smem_u32(sAl);
    unsigned bBh = smem_u32(sBh), bBl = smem_u32(sBl);

    int frow = tid >> 1;
    int fcol = (tid & 1) * 16;
    int grow = rowBase + frow;

    for (int kk = 0; kk < 128; kk += 32) {
        {
            float t[16];
            if (grow < NN) {
                const float4* src = (const float4*)(A + (size_t)grow * 128 + kk + fcol);
#pragma unroll
                for (int i = 0; i < 4; i++) {
                    float4 v = src[i];
                    t[i * 4 + 0] = v.x; t[i * 4 + 1] = v.y;
                    t[i * 4 + 2] = v.z; t[i * 4 + 3] = v.w;
                }
            } else {
#pragma unroll
                for (int i = 0; i < 16; i++) t[i] = 0.f;
            }
            unsigned short hb[16], lb[16];
#pragma unroll
            for (int i = 0; i < 16; i++) {
                hb[i] = bf16rne(t[i]);
                lb[i] = bf16rne(t[i] - bf16tof(hb[i]));
            }
            uint4* dh = (uint4*)&sAh[frow * TS + fcol];
            uint4* dl = (uint4*)&sAl[frow * TS + fcol];
            dh[0] = ((uint4*)hb)[0]; dh[1] = ((uint4*)hb)[1];
            dl[0] = ((uint4*)lb)[0]; dl[1] = ((uint4*)lb)[1];
        }
        {
            const uint4* sh = (const uint4*)(WTh + (size_t)(nBase + frow) * 128 + kk + fcol);
            const uint4* sl = (const uint4*)(WTl + (size_t)(nBase + frow) * 128 + kk + fcol);
            uint4* dh = (uint4*)&sBh[frow * TS + fcol];
            uint4* dl = (uint4*)&sBl[frow * TS + fcol];
            dh[0] = sh[0]; dh[1] = sh[1];
            dl[0] = sl[0]; dl[1] = sl[1];
        }
        __syncthreads();

#pragma unroll
        for (int ks = 0; ks < 32; ks += 16) {
            unsigned aH[4][4], aL[4][4];
#pragma unroll
            for (int mi = 0; mi < 4; mi++) {
                int row = wm * 64 + mi * 16 + (lane & 15);
                int col = ks + (lane >> 4) * 8;
                unsigned off = (unsigned)(row * TS + col) * 2;
                ldm_x4(aH[mi], bAh + off);
                ldm_x4(aL[mi], bAl + off);
            }
            unsigned bH[4][2], bL[4][2];
#pragma unroll
            for (int nip = 0; nip < 4; nip += 2) {
                int nrow = wn * 32 + nip * 8 + ((lane >> 4) & 1) * 8 + (lane & 7);
                int kcol = ks + ((lane >> 3) & 1) * 8;
                unsigned off = (unsigned)(nrow * TS + kcol) * 2;
                unsigned r[4];
                ldm_x4(r, bBh + off);
                bH[nip][0] = r[0]; bH[nip][1] = r[1];
                bH[nip + 1][0] = r[2]; bH[nip + 1][1] = r[3];
                ldm_x4(r, bBl + off);
                bL[nip][0] = r[0]; bL[nip][1] = r[1];
                bL[nip + 1][0] = r[2]; bL[nip + 1][1] = r[3];
            }
#pragma unroll
            for (int mi = 0; mi < 4; mi++)
#pragma unroll
                for (int ni = 0; ni < 4; ni++) {
                    mma16816(acc[mi][ni], aH[mi], bH[ni][0], bH[ni][1]);
                    mma16816(acc[mi][ni], aL[mi], bH[ni][0], bH[ni][1]);
                    mma16816(acc[mi][ni], aH[mi], bL[ni][0], bL[ni][1]);
                }
        }
        __syncthreads();
    }

    float* outL = which ? (float*)d_t2l : (float*)d_t1l;
    float* outR = which ? (float*)d_t2r : (float*)d_t1r;
#pragma unroll
    for (int mi = 0; mi < 4; mi++) {
        int r0 = rowBase + wm * 64 + mi * 16 + (lane >> 2);
#pragma unroll
        for (int ni = 0; ni < 4; ni++) {
            int cl = wn * 32 + ni * 8 + (lane & 3) * 2;
            if (!which) {
                float* dst = (nBase == 0) ? outL : outR;
                if (r0 < NN)
                    *(float2*)(dst + (size_t)r0 * 128 + cl) =
                        make_float2(acc[mi][ni][0], acc[mi][ni][1]);
                if (r0 + 8 < NN)
                    *(float2*)(dst + (size_t)(r0 + 8) * 128 + cl) =
                        make_float2(acc[mi][ni][2], acc[mi][ni][3]);
            } else {
                float* base = (cl < 64) ? (outL + cl) : (outR + (cl - 64));
                if (r0 < NN)
                    *(float2*)(base + (size_t)r0 * 64) =
                        make_float2(acc[mi][ni][0], acc[mi][ni][1]);
                if (r0 + 8 < NN)
                    *(float2*)(base + (size_t)(r0 + 8) * 64) =
                        make_float2(acc[mi][ni][2], acc[mi][ni][3]);
            }
        }
    }
}

// ---------------- fused kernel: CSR build (blocks 0..147) + layer1 GEMM (rest) ------------
__global__ void k_fused(const float* __restrict__ x, const void* __restrict__ ei) {
    int bid = blockIdx.x;
    if (bid >= CSRB) {
        int gb = bid - CSRB;
        gemm_body(x, (const unsigned short*)d_wt1h4, (const unsigned short*)d_wt1lo4,
                  0, (gb >> 1) * 128, (gb & 1) * 128);
        return;
    }
    // ---------------- CSR role ----------------
    __shared__ int s[256];
    int tid = threadIdx.x;
    const int NT = CSRB * 256;
    int g = bid * 256 + tid;

    // phase A: zero counters; block 0 probes edge dtype
    for (int i = g; i < NN; i += NT) { d_cnt[i] = 0; d_cursor[i] = 0; }
    if (bid == 0) {
        __shared__ int nonzero;
        if (tid == 0) nonzero = 0;
        __syncthreads();
        const int* e32 = (const int*)ei;
        for (int j = tid; j < 4096; j += 256)
            if (e32[2 * j + 1] != 0) nonzero = 1;
        __syncthreads();
        if (tid == 0) d_is64 = (nonzero == 0) ? 1 : 0;
    }
    grid_bar(0);

    // phase B: degree count
    for (int e = g; e < EE; e += NT)
        atomicAdd(&d_cnt[edge_id(ei, 1, e)], 1);
    grid_bar(1);

    // phase C: per-segment exclusive scan (segments of 256)
    for (int seg = bid; seg < NSEG; seg += CSRB) {
        int i = seg * 256 + tid;
        int v = (i < NN) ? d_cnt[i] : 0;
        s[tid] = v;
        __syncthreads();
        for (int off = 1; off < 256; off <<= 1) {
            int t2 = (tid >= off) ? s[tid - off] : 0;
            __syncthreads();
            s[tid] += t2;
            __syncthreads();
        }
        if (i < NN) d_rowptr[i] = s[tid] - v;
        if (tid == 255) d_bsum[seg] = s[255];
        __syncthreads();
    }
    grid_bar(2);

    // phase D: redundant scan of segment sums + apply prefix
    s[tid] = (tid < NSEG) ? d_bsum[tid] : 0;
    __syncthreads();
    for (int off = 1; off < 256; off <<= 1) {
        int t2 = (tid >= off) ? s[tid - off] : 0;
        __syncthreads();
        s[tid] += t2;
        __syncthreads();
    }
    for (int seg = bid; seg < NSEG; seg += CSRB) {
        int prefix = (seg == 0) ? 0 : s[seg - 1];
        int i = seg * 256 + tid;
        if (i < NN) d_rowptr[i] += prefix;
    }
    if (bid == 0 && tid == 0) d_rowptr[NN] = EE;
    grid_bar(3);

    // phase E: fill columns
    for (int e = g; e < EE; e += NT) {
        int d = edge_id(ei, 1, e);
        int sc = edge_id(ei, 0, e);
        int p = atomicAdd(&d_cursor[d], 1);
        d_col[d_rowptr[d] + p] = sc;
    }
}

// ---------------- layer2 GEMM launcher ----------------
__global__ void __launch_bounds__(256) k_gemm_l2() {
    gemm_body((const float*)d_h1, (const unsigned short*)d_wt2h4,
              (const unsigned short*)d_wt2lo4, 1, blockIdx.x * 128, 0);
}

// ---------- layer1 agg: h1 = relu(mean_nbr(t1l) + t1r[self] + b1l); warp per node ---------
__global__ void k_agg1(const float* __restrict__ b1l) {
    int idx = blockIdx.x * blockDim.x + threadIdx.x;
    int node = idx >> 5;
    int lane = idx & 31;
    if (node >= NN) return;
    int beg = d_rowptr[node], end = d_rowptr[node + 1];
    float4 acc = make_float4(0.f, 0.f, 0.f, 0.f);
    for (int j = beg; j < end; j++) {
        int s = d_col[j];
        float4 v = d_t1l[(size_t)s * 32 + lane];
        acc.x += v.x; acc.y += v.y; acc.z += v.z; acc.w += v.w;
    }
    int c = end - beg;
    float inv = 1.0f / (float)(c > 0 ? c : 1);
    float4 self = d_t1r[(size_t)node * 32 + lane];
    float4 b = ((const float4*)b1l)[lane];
    float4 o;
    o.x = fmaxf(acc.x * inv + self.x + b.x, 0.f);
    o.y = fmaxf(acc.y * inv + self.y + b.y, 0.f);
    o.z = fmaxf(acc.z * inv + self.z + b.z, 0.f);
    o.w = fmaxf(acc.w * inv + self.w + b.w, 0.f);
    d_h1[(size_t)node * 32 + lane] = o;
}

// ------- layer2 agg + bias + softmax: h2 = softmax(mean_nbr(t2l) + t2r[self] + b2l) -------
__global__ void k_agg2sm(const float* __restrict__ b2l) {
    int idx = blockIdx.x * blockDim.x + threadIdx.x;
    int node = idx >> 5;
    int lane = idx & 31;
    if (node >= NN) return;
    int beg = d_rowptr[node], end = d_rowptr[node + 1];
    const float2* t2 = (const float2*)d_t2l;
    float ax = 0.f, ay = 0.f;
    for (int j = beg; j < end; j++) {
        int s = d_col[j];
        float2 v = t2[(size_t)s * 32 + lane];
        ax += v.x; ay += v.y;
    }
    int c = end - beg;
    float inv = 1.0f / (float)(c > 0 ? c : 1);
    float2 self = ((const float2*)d_t2r)[(size_t)node * 32 + lane];
    float2 b = ((const float2*)b2l)[lane];
    float vx = ax * inv + self.x + b.x;
    float vy = ay * inv + self.y + b.y;
    float m = fmaxf(vx, vy);
    for (int o = 16; o > 0; o >>= 1) m = fmaxf(m, __shfl_xor_sync(0xffffffffu, m, o));
    float ex = __expf(vx - m), ey = __expf(vy - m);
    float sum = ex + ey;
    for (int o = 16; o > 0; o >>= 1) sum += __shfl_xor_sync(0xffffffffu, sum, o);
    float is = 1.0f / sum;
    ((float2*)d_h2)[(size_t)node * 32 + lane] = make_float2(ex * is, ey * is);
}

// ---------------- GCN GEMM (FFMA): y = (h2 @ Wg) * dinv[row]; M=NN, N=64, K=64 ------------
__global__ void __launch_bounds__(256) k_gemm_gcn(const float* __restrict__ Wg) {
    __shared__ float As[64][17];
    __shared__ float Ws[16][64];
    int tid = threadIdx.x;
    int rowBase = blockIdx.x * 64;
    int rg = tid >> 4;
    int cg = tid & 15;
    float acc[4][4];
#pragma unroll
    for (int i = 0; i < 4; i++)
#pragma unroll
        for (int j = 0; j < 4; j++) acc[i][j] = 0.f;

    int lr = tid >> 2;
    int lc = (tid & 3) * 4;
    bool lvalid = (rowBase + lr) < NN;
    const float* A = (const float*)d_h2;

    for (int kk = 0; kk < 64; kk += 16) {
        float4 va = make_float4(0.f, 0.f, 0.f, 0.f);
        if (lvalid) va = *(const float4*)(A + (size_t)(rowBase + lr) * 64 + kk + lc);
        As[lr][lc + 0] = va.x; As[lr][lc + 1] = va.y;
        As[lr][lc + 2] = va.z; As[lr][lc + 3] = va.w;
        {
            int wr = tid >> 4;
            int wc = (tid & 15) * 4;
            *(float4*)&Ws[wr][wc] = *(const float4*)(Wg + (size_t)(kk + wr) * 64 + wc);
        }
        __syncthreads();
#pragma unroll
        for (int k = 0; k < 16; k++) {
            float4 bv = *(const float4*)&Ws[k][cg * 4];
#pragma unroll
            for (int i = 0; i < 4; i++) {
                float a = As[rg * 4 + i][k];
                acc[i][0] += a * bv.x;
                acc[i][1] += a * bv.y;
                acc[i][2] += a * bv.z;
                acc[i][3] += a * bv.w;
            }
        }
        __syncthreads();
    }
#pragma unroll
    for (int i = 0; i < 4; i++) {
        int r = rowBase + rg * 4 + i;
        if (r < NN) {
            float dinv = rsqrtf((float)(d_cnt[r] + 1));
            float4 v = make_float4(acc[i][0] * dinv, acc[i][1] * dinv,
                                   acc[i][2] * dinv, acc[i][3] * dinv);
            d_y[(size_t)r * 16 + cg] = v;
        }
    }
}

// ---------------- GCN aggregation: out[i] = dinv[i]*(y[i] + sum_nbr y[j]) + bg ------------
__global__ void k_gcn_agg(const float* __restrict__ bg, float* __restrict__ out) {
    int idx = blockIdx.x * blockDim.x + threadIdx.x;
    int node = idx >> 4;
    int lane = idx & 15;
    if (node >= NN) return;
    float4 acc = d_y[(size_t)node * 16 + lane];
    int beg = d_rowptr[node], end = d_rowptr[node + 1];
    for (int j = beg; j < end; j++) {
        int s = d_col[j];
        float4 v = d_y[(size_t)s * 16 + lane];
        acc.x += v.x; acc.y += v.y; acc.z += v.z; acc.w += v.w;
    }
    float dinv = rsqrtf((float)(d_cnt[node] + 1));
    float4 b = ((const float4*)bg)[lane];
    float4 o;
    o.x = acc.x * dinv + b.x;
    o.y = acc.y * dinv + b.y;
    o.z = acc.z * dinv + b.z;
    o.w = acc.w * dinv + b.w;
    ((float4*)out)[(size_t)node * 16 + lane] = o;
}

// ---------------- launch ----------------
extern "C" void kernel_launch(void* const* d_in, const int* in_sizes, int n_in,
                              void* d_out, int out_size) {
    const float* x = (const float*)d_in[0];
    const void* ei = d_in[1];
    const float* W1l = (const float*)d_in[2];
    const float* b1l = (const float*)d_in[3];
    const float* W1r = (const float*)d_in[4];
    const float* W2l = (const float*)d_in[5];
    const float* b2l = (const float*)d_in[6];
    const float* W2r = (const float*)d_in[7];
    const float* Wg  = (const float*)d_in[8];
    const float* bg  = (const float*)d_in[9];
    float* out = (float*)d_out;

    const int GT = (NN + 127) / 128;  // 391

    // weight prep, then fused CSR-build + layer1 GEMM (CSR hidden under GEMM)
    k_prep_w<<<128, 256>>>(W1l, W1r, W2l, W2r);
    k_fused<<<CSRB + GT * 2, 256>>>(x, ei);

    // layer 1 epilogue: fused agg + bias + relu
    k_agg1<<<(NN * 32 + 255) / 256, 256>>>(b1l);

    // layer 2: mma GEMM, then fused agg + bias + softmax
    k_gemm_l2<<<GT, 256>>>();
    k_agg2sm<<<(NN * 32 + 255) / 256, 256>>>(b2l);

    // GCN: y = (h2 @ Wg) * dinv (FFMA), then normalized aggregation + bias
    k_gemm_gcn<<<(NN + 63) / 64, 256>>>(Wg);
    k_gcn_agg<<<(NN * 16 + 255) / 256, 256>>>(bg, out);
}